// round 3
// baseline (speedup 1.0000x reference)
#include <cuda_runtime.h>
#include <math.h>
#include <stdint.h>

#define Bsz 8192
#define Knod 16
#define Eedg 64
#define FIN 300
#define FOUT 64
#define ALPHA 1.0f
#define BETA 0.6f

// per-graph partial results (no big scratch needed anymore)
static __device__ float g_ssq1[Bsz];
static __device__ float g_ssq2[Bsz];
static __device__ float g_lt1[Bsz];
static __device__ float g_lt2[Bsz];
static __device__ float g_contr[Bsz];
static __device__ float g_gen;

// ---------------- packed f32x2 helpers ----------------
__device__ __forceinline__ uint64_t pk(float lo, float hi) {
    union { float2 f; uint64_t u; } c; c.f = make_float2(lo, hi); return c.u;
}
__device__ __forceinline__ float2 upk(uint64_t v) {
    union { float2 f; uint64_t u; } c; c.u = v; return c.f;
}
__device__ __forceinline__ uint64_t bcast2(float x) {
    uint64_t r; uint32_t xi = __float_as_uint(x);
    asm("mov.b64 %0, {%1, %1};" : "=l"(r) : "r"(xi));
    return r;
}
__device__ __forceinline__ void ffma2(uint64_t& d, uint64_t a, uint64_t b) {
    asm("fma.rn.f32x2 %0, %1, %2, %0;" : "+l"(d) : "l"(a), "l"(b));
}

// ---------------- shared-memory layout (floats) ----------------
#define OFF_FEAT 0        // 3*16*304 = 14592   (reused as sWb 64x65 after GEMM)
#define OFF_Y    14592    // 3*16*64  = 3072
#define OFF_AGP  17664    // 4*1024   = 4096
#define OFF_H    21760    // 2*1024   = 2048
#define OFF_HD   23808    // 2*304    = 608
#define OFF_RED  24416    // 256
#define OFF_POOL 24672    // 3*64 = 192
#define OFF_A    24864    // 2*64 = 128
#define OFF_U    24992    // 64
#define OFF_V2   25056    // 128 (interleaved pairs)
#define OFF_BENC 25184    // 64
#define OFF_WE   25248    // 64
#define OFF_SRC  25312    // 64 (int)
#define OFF_DST  25376    // 64 (int)
#define OFF_DEGS 25440    // 16
#define OFF_DEGD 25456    // 16
#define OFF_INV  25472    // 16
#define OFF_SCAL 25488    // 16
#define SMEM_FLOATS 25504
#define SMEM_BYTES (SMEM_FLOATS * 4)

__device__ __forceinline__ float bred256(float v, float* sRed) {
    int tid = threadIdx.x;
    sRed[tid] = v;
    __syncthreads();
#pragma unroll
    for (int s = 128; s > 0; s >>= 1) {
        if (tid < s) sRed[tid] += sRed[tid + s];
        __syncthreads();
    }
    float r = sRed[0];
    __syncthreads();
    return r;
}

// ---------------------------------------------------------------------------
// Fused per-graph kernel: encoder GEMM + SpMM + disc + decoder. 256 thr/CTA.
// ---------------------------------------------------------------------------
__global__ void __launch_bounds__(256, 2) fused_kernel(
    const float* __restrict__ feat_p1, const float* __restrict__ feat_p2,
    const float* __restrict__ feat_n,
    const float* __restrict__ w_p1, const float* __restrict__ w_p2,
    const float* __restrict__ w_n,
    const float* __restrict__ W_enc, const float* __restrict__ b_enc,
    const float* __restrict__ W_dec, const float* __restrict__ b_dec,
    const float* __restrict__ W_bil, const float* __restrict__ b_bil,
    const int* __restrict__ src_p1, const int* __restrict__ dst_p1,
    const int* __restrict__ src_p2, const int* __restrict__ dst_p2,
    const int* __restrict__ src_n,  const int* __restrict__ dst_n)
{
    extern __shared__ float sm[];
    const int b = blockIdx.x;
    const int tid = threadIdx.x;

    float* sFeat = sm + OFF_FEAT;
    float* sWb   = sm + OFF_FEAT;   // reused after GEMM
    float* sY    = sm + OFF_Y;
    float* sAgP  = sm + OFF_AGP;
    float* sH    = sm + OFF_H;
    float* sHd   = sm + OFF_HD;
    float* sRed  = sm + OFF_RED;
    float* sPool = sm + OFF_POOL;
    float* sA    = sm + OFF_A;
    float* sU    = sm + OFF_U;
    float* sV2   = sm + OFF_V2;
    float* sBenc = sm + OFF_BENC;
    float* sWe   = sm + OFF_WE;
    int*   sSrcI = (int*)(sm + OFF_SRC);
    int*   sDstI = (int*)(sm + OFF_DST);
    float* sDegS = sm + OFF_DEGS;
    float* sDegD = sm + OFF_DEGD;
    float* sInv  = sm + OFF_INV;
    float* sScal = sm + OFF_SCAL;

    const float* feats[3] = { feat_p1 + (long)b * (Knod * FIN),
                              feat_p2 + (long)b * (Knod * FIN),
                              feat_n  + (long)b * (Knod * FIN) };
    const float* wps[3] = { w_p1 + (long)b * Eedg, w_p2 + (long)b * Eedg, w_n + (long)b * Eedg };
    const int* sps[3] = { src_p1 + (long)b * Eedg, src_p2 + (long)b * Eedg, src_n + (long)b * Eedg };
    const int* dps[3] = { dst_p1 + (long)b * Eedg, dst_p2 + (long)b * Eedg, dst_n + (long)b * Eedg };

    // ---- stage feat tiles into smem (rows of 300 = 75 float4, stride 304) ----
#pragma unroll
    for (int s = 0; s < 3; s++) {
        const float4* src4 = (const float4*)feats[s];
        for (int j = tid; j < Knod * 75; j += 256) {
            float4 v = src4[j];
            int r = j / 75;
            int c4 = (j - r * 75) * 4;
            *(float4*)&sFeat[(s * Knod + r) * 304 + c4] = v;
        }
    }
    if (tid < FOUT) sBenc[tid] = b_enc[tid];
    __syncthreads();

    // ---- encoder GEMM: Y[s][16][64] = feat[s] @ W_enc, f32x2 packed ----
    {
        const int n4 = (tid & 15) * 4;
        const int r  = tid >> 4;
        const float4* Wv = (const float4*)W_enc;
        const int wi = n4 >> 2;
        uint64_t acc[3][2];
#pragma unroll
        for (int s = 0; s < 3; s++) { acc[s][0] = 0ull; acc[s][1] = 0ull; }

        for (int kk = 0; kk < FIN; kk += 4) {
            float4 w0 = __ldg(&Wv[(kk + 0) * 16 + wi]);
            float4 w1 = __ldg(&Wv[(kk + 1) * 16 + wi]);
            float4 w2 = __ldg(&Wv[(kk + 2) * 16 + wi]);
            float4 w3 = __ldg(&Wv[(kk + 3) * 16 + wi]);
            uint64_t wp00 = pk(w0.x, w0.y), wp01 = pk(w0.z, w0.w);
            uint64_t wp10 = pk(w1.x, w1.y), wp11 = pk(w1.z, w1.w);
            uint64_t wp20 = pk(w2.x, w2.y), wp21 = pk(w2.z, w2.w);
            uint64_t wp30 = pk(w3.x, w3.y), wp31 = pk(w3.z, w3.w);
#pragma unroll
            for (int s = 0; s < 3; s++) {
                float4 a = *(const float4*)&sFeat[(s * Knod + r) * 304 + kk];
                uint64_t a0 = bcast2(a.x), a1 = bcast2(a.y);
                uint64_t a2 = bcast2(a.z), a3 = bcast2(a.w);
                ffma2(acc[s][0], a0, wp00); ffma2(acc[s][1], a0, wp01);
                ffma2(acc[s][0], a1, wp10); ffma2(acc[s][1], a1, wp11);
                ffma2(acc[s][0], a2, wp20); ffma2(acc[s][1], a2, wp21);
                ffma2(acc[s][0], a3, wp30); ffma2(acc[s][1], a3, wp31);
            }
        }
#pragma unroll
        for (int s = 0; s < 3; s++) {
            float2 lo = upk(acc[s][0]), hi = upk(acc[s][1]);
            float4 v = make_float4(lo.x, lo.y, hi.x, hi.y);
            *(float4*)&sY[(s * Knod + r) * FOUT + n4] = v;
        }
    }
    __syncthreads();

    // sFeat dead -> load W_bil into its space (padded 64x65)
    for (int i = tid; i < FOUT * FOUT; i += 256)
        sWb[(i >> 6) * 65 + (i & 63)] = W_bil[i];
    // (consumed only after later __syncthreads)

    // ---- per-sample encoder pipeline ----
    for (int s = 0; s < 3; s++) {
        if (tid < Eedg) {
            sSrcI[tid] = sps[s][tid];
            sDstI[tid] = dps[s][tid];
            sWe[tid]   = wps[s][tid];
        }
        for (int i = tid; i < 4096; i += 256) sAgP[i] = 0.f;
        __syncthreads();

        // SpMM: 4 edge-groups x 64 features, deterministic partials
        {
            const int g = tid >> 6, f = tid & 63;
            float* P = sAgP + (g << 10);
            const float* Ys = sY + s * (Knod * FOUT);
#pragma unroll
            for (int j = 0; j < 16; j++) {
                int e = g * 16 + j;
                int se = sSrcI[e];
                if (se != 0) P[sDstI[e] * FOUT + f] += sWe[e] * Ys[se * FOUT + f];
            }
        }
        __syncthreads();

        // combine + bias + relu -> h in sAgP[0..1023]
        for (int i = tid; i < Knod * FOUT; i += 256) {
            float v = sAgP[i] + sAgP[1024 + i] + sAgP[2048 + i] + sAgP[3072 + i] + sBenc[i & 63];
            sAgP[i] = fmaxf(v, 0.f);
        }
        __syncthreads();
        float* hcur = sAgP;

        // pool (raw h mean over nodes)
        if (tid < FOUT) {
            float p = 0.f;
#pragma unroll
            for (int k = 0; k < Knod; k++) p += hcur[k * FOUT + tid];
            sPool[s * FOUT + tid] = p * (1.f / Knod);
        }

        if (s < 2) {
            // per-row inverse norms (128 threads: 8 per row)
            if (tid < 128) {
                int k = tid >> 3, j = tid & 7;
                float ssq = 0.f;
                for (int f = j; f < FOUT; f += 8) {
                    float v = hcur[k * FOUT + f];
                    ssq += v * v;
                }
                ssq += __shfl_xor_sync(0xffffffff, ssq, 1);
                ssq += __shfl_xor_sync(0xffffffff, ssq, 2);
                ssq += __shfl_xor_sync(0xffffffff, ssq, 4);
                if (j == 0) sInv[k] = 1.f / fmaxf(sqrtf(ssq), 1e-12f);
            }
            __syncthreads();
            for (int i = tid; i < Knod * FOUT; i += 256)
                sH[s * (Knod * FOUT) + i] = hcur[i] * sInv[i >> 6];

            // anchor = l2n(relu(Y[0] + b))
            if (tid < FOUT) sA[s * FOUT + tid] = fmaxf(sY[s * (Knod * FOUT) + tid] + sBenc[tid], 0.f);
            __syncthreads();
            {
                float v = (tid < FOUT) ? sA[s * FOUT + tid] : 0.f;
                float ssq = bred256(v * v, sRed);
                float inv = 1.f / fmaxf(sqrtf(ssq), 1e-12f);
                if (tid < FOUT) sA[s * FOUT + tid] *= inv;
            }
        }
        __syncthreads();

        // pool l2n
        {
            float v = (tid < FOUT) ? sPool[s * FOUT + tid] : 0.f;
            float ssq = bred256(v * v, sRed);
            float inv = 1.f / fmaxf(sqrtf(ssq), 1e-12f);
            if (tid < FOUT) sPool[s * FOUT + tid] *= inv;
        }
        __syncthreads();
    }

    // ---- discriminators ----
    const float bb = __ldg(b_bil);
    for (int t = 0; t < 2; t++) {
        {
            const int n = tid & 63, q = tid >> 6;
            float u = 0.f;
#pragma unroll
            for (int k = 0; k < 16; k++) u += sWb[n * 65 + (q * 16 + k)] * sA[t * FOUT + (q * 16 + k)];
            sRed[q * 64 + n] = u;
        }
        __syncthreads();
        if (tid < FOUT) sU[tid] = sRed[tid] + sRed[64 + tid] + sRed[128 + tid] + sRed[192 + tid];
        __syncthreads();
        float dps = bred256((tid < FOUT) ? sPool[t * FOUT + tid] * sU[tid] : 0.f, sRed);
        float dns = bred256((tid < FOUT) ? sPool[2 * FOUT + tid] * sU[tid] : 0.f, sRed);
        if (tid == 0) {
            sScal[t]     = 1.f / (1.f + expf(-(dps + bb)));
            sScal[2 + t] = 1.f / (1.f + expf(-(dns + bb)));
        }
        __syncthreads();
    }

    // ---- decoders: only anchor row (dst==0) matters ----
    for (int s = 0; s < 2; s++) {
        if (tid < Eedg) {
            sSrcI[tid] = sps[s][tid];
            sDstI[tid] = dps[s][tid];
            sWe[tid]   = wps[s][tid];
        }
        if (tid < Knod) { sDegS[tid] = 0.f; sDegD[tid] = 0.f; }
        __syncthreads();
        if (tid < Eedg) {
            atomicAdd(&sDegS[sSrcI[tid]], 1.f);   // integer-valued: order-independent
            atomicAdd(&sDegD[sDstI[tid]], 1.f);
        }
        __syncthreads();
        if (tid < FOUT) {
            float v = 0.f;
            for (int e = 0; e < Eedg; e++) {
                if (sDstI[e] == 0) {
                    int se = sSrcI[e];
                    v += sWe[e] * rsqrtf(fmaxf(sDegS[se], 1.f)) * sH[s * (Knod * FOUT) + se * FOUT + tid];
                }
            }
            sV2[2 * tid + s] = v;
        }
        if (tid == 0) sScal[4 + s] = rsqrtf(fmaxf(sDegD[0], 1.f));
        __syncthreads();
    }

    // hd = relu((v @ W_dec) * ndst0 + b_dec), both decoders packed f32x2
    {
        const float nd0 = sScal[4], nd1 = sScal[5];
#pragma unroll
        for (int c = 0; c < 2; c++) {
            int i = tid + c * 256;
            if (i < FIN) {
                uint64_t acc = 0ull;
#pragma unroll 16
                for (int f = 0; f < FOUT; f++) {
                    float w = __ldg(&W_dec[f * FIN + i]);
                    uint64_t vp = *(const uint64_t*)&sV2[2 * f];
                    ffma2(acc, bcast2(w), vp);
                }
                float2 a = upk(acc);
                float bd = __ldg(&b_dec[i]);
                sHd[i]       = fmaxf(a.x * nd0 + bd, 0.f);
                sHd[304 + i] = fmaxf(a.y * nd1 + bd, 0.f);
            }
        }
    }
    __syncthreads();

    // norms of hd rows
    float l0 = 0.f, l1 = 0.f;
#pragma unroll
    for (int c = 0; c < 2; c++) {
        int i = tid + c * 256;
        if (i < FIN) { l0 += sHd[i] * sHd[i]; l1 += sHd[304 + i] * sHd[304 + i]; }
    }
    float n0 = bred256(l0, sRed);
    float n1 = bred256(l1, sRed);
    float inv0 = 1.f / fmaxf(sqrtf(n0), 1e-12f);
    float inv1 = 1.f / fmaxf(sqrtf(n1), 1e-12f);

    // squared error vs original anchor features
    const float* o0 = feats[0];   // row 0
    const float* o1 = feats[1];
    float e0 = 0.f, e1 = 0.f;
#pragma unroll
    for (int c = 0; c < 2; c++) {
        int i = tid + c * 256;
        if (i < FIN) {
            float d0 = sHd[i] * inv0 - __ldg(&o0[i]);
            float d1 = sHd[304 + i] * inv1 - __ldg(&o1[i]);
            e0 += d0 * d0;
            e1 += d1 * d1;
        }
    }
    float S0 = bred256(e0, sRed);
    float S1 = bred256(e1, sRed);

    if (tid == 0) {
        float ps1 = sScal[0], ps2 = sScal[1], ns1 = sScal[2], ns2 = sScal[3];
        g_ssq1[b] = S0;
        g_ssq2[b] = S1;
        g_lt1[b] = logf(ps1) + logf(1.f - ns1);
        g_lt2[b] = logf(ps2) + logf(1.f - ns2);
        g_contr[b] = (ns1 - ps1 + 1.f) * 0.5f + (ns2 - ps2 + 1.f) * 0.5f;
    }
}

// ---------------------------------------------------------------------------
// finalize: L (out[0]) and gen scalar
// ---------------------------------------------------------------------------
__global__ void __launch_bounds__(256) finalize_kernel(float* out) {
    __shared__ float sR[256 * 4];
    int tid = threadIdx.x;
    float a = 0.f, c = 0.f, m1 = 0.f, m2 = 0.f;
    for (int i = tid; i < Bsz; i += 256) {
        a += g_ssq1[i];
        c += g_ssq2[i];
        m1 += g_lt1[i];
        m2 += g_lt2[i];
    }
    sR[tid] = a; sR[256 + tid] = c; sR[512 + tid] = m1; sR[768 + tid] = m2;
    __syncthreads();
    for (int s = 128; s > 0; s >>= 1) {
        if (tid < s) {
            sR[tid] += sR[tid + s];
            sR[256 + tid] += sR[256 + tid + s];
            sR[512 + tid] += sR[512 + tid + s];
            sR[768 + tid] += sR[768 + tid + s];
        }
        __syncthreads();
    }
    if (tid == 0) {
        float Ssq1 = sR[0], Ssq2 = sR[256], M1 = sR[512], M2 = sR[768];
        float m1m = M1 / (float)Bsz, m2m = M2 / (float)Bsz;
        float L_con = -(m1m + m2m) * 0.25f;
        float L_gen = (Ssq1 + Ssq2) / (2.f * (float)Bsz * (float)FIN);
        out[0] = ALPHA * L_con + BETA * L_gen;
        g_gen = (sqrtf(Ssq1) + sqrtf(Ssq2)) / (2.f * sqrtf((float)FIN));
    }
}

__global__ void scores_kernel(float* out) {
    int i = blockIdx.x * blockDim.x + threadIdx.x;
    if (i < Bsz) out[1 + i] = ALPHA * g_contr[i] + BETA * g_gen;
}

// ---------------------------------------------------------------------------
extern "C" void kernel_launch(void* const* d_in, const int* in_sizes, int n_in,
                              void* d_out, int out_size) {
    const float* feat_p1 = (const float*)d_in[0];
    const float* feat_p2 = (const float*)d_in[1];
    const float* feat_n  = (const float*)d_in[2];
    const float* w_p1    = (const float*)d_in[3];
    const float* w_p2    = (const float*)d_in[4];
    const float* w_n     = (const float*)d_in[5];
    const float* W_enc   = (const float*)d_in[6];
    const float* b_enc   = (const float*)d_in[7];
    const float* W_dec   = (const float*)d_in[8];
    const float* b_dec   = (const float*)d_in[9];
    const float* W_bil   = (const float*)d_in[10];
    const float* b_bil   = (const float*)d_in[11];
    const int* src_p1 = (const int*)d_in[12];
    const int* dst_p1 = (const int*)d_in[13];
    const int* src_p2 = (const int*)d_in[14];
    const int* dst_p2 = (const int*)d_in[15];
    const int* src_n  = (const int*)d_in[16];
    const int* dst_n  = (const int*)d_in[17];
    float* out = (float*)d_out;

    cudaFuncSetAttribute(fused_kernel, cudaFuncAttributeMaxDynamicSharedMemorySize, SMEM_BYTES);

    fused_kernel<<<Bsz, 256, SMEM_BYTES>>>(
        feat_p1, feat_p2, feat_n, w_p1, w_p2, w_n,
        W_enc, b_enc, W_dec, b_dec, W_bil, b_bil,
        src_p1, dst_p1, src_p2, dst_p2, src_n, dst_n);

    finalize_kernel<<<1, 256>>>(out);
    scores_kernel<<<(Bsz + 255) / 256, 256>>>(out);
}

// round 5
// speedup vs baseline: 1.8074x; 1.8074x over previous
#include <cuda_runtime.h>
#include <math.h>
#include <stdint.h>

#define Bsz 8192
#define Knod 16
#define Eedg 64
#define FIN 300
#define FOUT 64
#define ALPHA 1.0f
#define BETA 0.6f

#define GEMM_GRID 384
#define NJOBS 3072          // 3 samples * 1024 row-blocks of 128

static __device__ float g_Y[(size_t)3 * Bsz * Knod * FOUT];   // ~100 MB scratch
static __device__ float g_ssq1[Bsz];
static __device__ float g_ssq2[Bsz];
static __device__ float g_lt1[Bsz];
static __device__ float g_lt2[Bsz];
static __device__ float g_contr[Bsz];
static __device__ float g_gen;

// ---------------- packed f32x2 helpers ----------------
__device__ __forceinline__ float2 upk(uint64_t v) {
    union { float2 f; uint64_t u; } c; c.u = v; return c.f;
}
__device__ __forceinline__ uint64_t bcast2(float x) {
    uint64_t r; uint32_t xi = __float_as_uint(x);
    asm("mov.b64 %0, {%1, %1};" : "=l"(r) : "r"(xi));
    return r;
}
__device__ __forceinline__ void ffma2(uint64_t& d, uint64_t a, uint64_t b) {
    asm("fma.rn.f32x2 %0, %1, %2, %0;" : "+l"(d) : "l"(a), "l"(b));
}
__device__ __forceinline__ float wred(float v) {
    v += __shfl_xor_sync(0xffffffffu, v, 16);
    v += __shfl_xor_sync(0xffffffffu, v, 8);
    v += __shfl_xor_sync(0xffffffffu, v, 4);
    v += __shfl_xor_sync(0xffffffffu, v, 2);
    v += __shfl_xor_sync(0xffffffffu, v, 1);
    return v;
}

// ===========================================================================
// Kernel 1: persistent GEMM  Y = feat @ W_enc  (M=3*131072, K=300, N=64)
// W_enc resident in smem; A double-buffered bk=20; f32x2 accumulators.
// ===========================================================================
#define SW_FLOATS 19200                  // 300*64
#define ATILE 2560                       // 20*128
#define GEMM_SMEM ((SW_FLOATS + 2 * ATILE) * 4)

__global__ void __launch_bounds__(256, 2) gemm_kernel(
    const float* __restrict__ f1, const float* __restrict__ f2,
    const float* __restrict__ fn, const float* __restrict__ W)
{
    extern __shared__ float sm[];
    float* sW = sm;                 // [300][64]
    float* sA = sm + SW_FLOATS;     // 2 x [20][128] transposed tiles

    const int tid = threadIdx.x;
    const int lane = tid & 31, warp = tid >> 5;

    // load W_enc once
    for (int j = tid; j < 4800; j += 256)
        *(float4*)&sW[4 * j] = __ldg(&((const float4*)W)[j]);

    // per-thread A-loader slots (640 float4 per tile; 2-3 per thread)
    const int r0 = tid / 5, q0 = tid % 5;
    const int j1 = tid + 256, r1 = j1 / 5, q1 = j1 % 5;
    const int j2 = tid + 512; const bool ok2 = (j2 < 640);
    const int r2 = j2 / 5, q2 = j2 % 5;
    const long gof0 = (long)r0 * FIN + 4 * q0;
    const long gof1 = (long)r1 * FIN + 4 * q1;
    const long gof2 = (long)r2 * FIN + 4 * q2;
    const int sof0 = 4 * q0 * 128 + r0;
    const int sof1 = 4 * q1 * 128 + r1;
    const int sof2 = 4 * q2 * 128 + r2;

    __syncthreads();

    for (int job = blockIdx.x; job < NJOBS; job += GEMM_GRID) {
        const int s = job >> 10, blk = job & 1023;
        const float* A = ((s == 0) ? f1 : (s == 1) ? f2 : fn) + (long)blk * 128 * FIN;

        float4 p0 = __ldg((const float4*)(A + gof0));
        float4 p1 = __ldg((const float4*)(A + gof1));
        float4 p2 = ok2 ? __ldg((const float4*)(A + gof2)) : make_float4(0.f, 0.f, 0.f, 0.f);

        uint64_t acc[4][4];
#pragma unroll
        for (int i = 0; i < 4; i++)
#pragma unroll
            for (int np = 0; np < 4; np++) acc[i][np] = 0ull;

#pragma unroll 1
        for (int it = 0; it < 15; it++) {
            float* buf = sA + (it & 1) * ATILE;
            // store staged tile (transposed As[k][m])
            buf[sof0] = p0.x; buf[sof0 + 128] = p0.y; buf[sof0 + 256] = p0.z; buf[sof0 + 384] = p0.w;
            buf[sof1] = p1.x; buf[sof1 + 128] = p1.y; buf[sof1 + 256] = p1.z; buf[sof1 + 384] = p1.w;
            if (ok2) { buf[sof2] = p2.x; buf[sof2 + 128] = p2.y; buf[sof2 + 256] = p2.z; buf[sof2 + 384] = p2.w; }
            __syncthreads();
            // prefetch next tile into regs
            if (it < 14) {
                const float* An = A + (it + 1) * 20;
                p0 = __ldg((const float4*)(An + gof0));
                p1 = __ldg((const float4*)(An + gof1));
                if (ok2) p2 = __ldg((const float4*)(An + gof2));
            }
            // compute
            const float* curA = buf + (lane << 2);
            const float* wk = sW + (it * 20) * 64 + (warp << 3);
#pragma unroll
            for (int k = 0; k < 20; k++) {
                float4 av = *(const float4*)(curA + k * 128);
                uint64_t w0 = *(const uint64_t*)(wk + k * 64);
                uint64_t w1 = *(const uint64_t*)(wk + k * 64 + 2);
                uint64_t w2 = *(const uint64_t*)(wk + k * 64 + 4);
                uint64_t w3 = *(const uint64_t*)(wk + k * 64 + 6);
                uint64_t a0 = bcast2(av.x), a1 = bcast2(av.y);
                uint64_t a2 = bcast2(av.z), a3 = bcast2(av.w);
                ffma2(acc[0][0], a0, w0); ffma2(acc[0][1], a0, w1);
                ffma2(acc[0][2], a0, w2); ffma2(acc[0][3], a0, w3);
                ffma2(acc[1][0], a1, w0); ffma2(acc[1][1], a1, w1);
                ffma2(acc[1][2], a1, w2); ffma2(acc[1][3], a1, w3);
                ffma2(acc[2][0], a2, w0); ffma2(acc[2][1], a2, w1);
                ffma2(acc[2][2], a2, w2); ffma2(acc[2][3], a2, w3);
                ffma2(acc[3][0], a3, w0); ffma2(acc[3][1], a3, w1);
                ffma2(acc[3][2], a3, w2); ffma2(acc[3][3], a3, w3);
            }
            __syncthreads();
        }
        // epilogue: rows 4*lane..+3, cols 8*warp..+7
        float* Yj = g_Y + ((size_t)s * (Bsz * Knod) + (size_t)blk * 128 + (lane << 2)) * 64 + (warp << 3);
#pragma unroll
        for (int i = 0; i < 4; i++)
#pragma unroll
            for (int np = 0; np < 4; np++)
                *(float2*)(Yj + i * 64 + 2 * np) = upk(acc[i][np]);
    }
}

// ===========================================================================
// Kernel 2: warp-per-graph pipeline; 8 graphs/CTA; CTA-cooperative decoder.
// ===========================================================================
#define GSTR 2752                        // floats per graph block
// per-graph offsets (floats)
#define OY    0                          // Y current sample [16][64]
#define OAGG  1024                       // agg -> normalized h; reused as hd[2][304]
#define OSRC  2048                       // int[64]
#define ODST  2112                       // int[64]
#define OWE   2176                       // float[64]
#define OA    2240                       // anchors [2][64]
#define OPOOL 2368                       // pools [3][64]
#define OV2   2560                       // v pairs: feature f -> floats 2f (dec0), 2f+1 (dec1)
#define OSCAL 2688                       // ps1 ps2 ns1 ns2 nd0 nd1
#define ODEG  2696                       // degS[16]
#define GK_SMEM ((8 * GSTR + 64 * 65) * 4)

__global__ void __launch_bounds__(256, 2) graph_kernel(
    const float* __restrict__ fp1, const float* __restrict__ fp2,
    const float* __restrict__ w_p1, const float* __restrict__ w_p2,
    const float* __restrict__ w_n,
    const float* __restrict__ b_enc, const float* __restrict__ W_dec,
    const float* __restrict__ b_dec, const float* __restrict__ W_bil,
    const float* __restrict__ b_bil,
    const int* __restrict__ sp1, const int* __restrict__ dp1,
    const int* __restrict__ sp2, const int* __restrict__ dp2,
    const int* __restrict__ spn, const int* __restrict__ dpn)
{
    extern __shared__ float sm[];
    float* sWb = sm + 8 * GSTR;          // [64][65]
    const int tid = threadIdx.x, lane = tid & 31, g = tid >> 5;
    const int b = blockIdx.x * 8 + g;
    float* G = sm + g * GSTR;
    int* Gsrc = (int*)(G + OSRC);
    int* Gdst = (int*)(G + ODST);
    float* Gwe = G + OWE;

    for (int j = tid; j < 4096; j += 256)
        sWb[(j >> 6) * 65 + (j & 63)] = __ldg(&W_bil[j]);
    __syncthreads();

    const float2 be = *(const float2*)&b_enc[2 * lane];

    const int* srcs[3] = { sp1 + (long)b * Eedg, sp2 + (long)b * Eedg, spn + (long)b * Eedg };
    const int* dsts[3] = { dp1 + (long)b * Eedg, dp2 + (long)b * Eedg, dpn + (long)b * Eedg };
    const float* wgts[3] = { w_p1 + (long)b * Eedg, w_p2 + (long)b * Eedg, w_n + (long)b * Eedg };

    for (int s = 0; s < 3; s++) {
        // edges
        Gsrc[lane] = __ldg(&srcs[s][lane]);  Gsrc[lane + 32] = __ldg(&srcs[s][lane + 32]);
        Gdst[lane] = __ldg(&dsts[s][lane]);  Gdst[lane + 32] = __ldg(&dsts[s][lane + 32]);
        Gwe[lane]  = __ldg(&wgts[s][lane]);  Gwe[lane + 32]  = __ldg(&wgts[s][lane + 32]);
        // Y tile (coalesced)
        const float4* Yf4 = (const float4*)(g_Y + ((size_t)s * (Bsz * Knod) + (size_t)b * Knod) * 64);
#pragma unroll
        for (int u = 0; u < 8; u++)
            *(float4*)&G[OY + 4 * (lane + 32 * u)] = __ldg(&Yf4[lane + 32 * u]);
        // zero agg (lane-private columns 2l,2l+1)
#pragma unroll
        for (int k = 0; k < Knod; k++)
            *(float2*)&G[OAGG + k * 64 + 2 * lane] = make_float2(0.f, 0.f);
        __syncwarp();

        // SpMM (skip src==0: its x-row is zero in the encoder)
        for (int e = 0; e < Eedg; e++) {
            int se = Gsrc[e];
            if (se != 0) {
                int de = Gdst[e]; float w = Gwe[e];
                float2 y = *(const float2*)&G[OY + se * 64 + 2 * lane];
                float2* ap = (float2*)&G[OAGG + de * 64 + 2 * lane];
                float2 a = *ap;
                a.x = fmaf(w, y.x, a.x); a.y = fmaf(w, y.y, a.y);
                *ap = a;
            }
        }

        // h = relu(agg + b); pool; (s<2) per-node norms + normalize in place
        float px = 0.f, py = 0.f;
        if (s < 2) {
            float2 h2[Knod];
            float ssq[Knod];
#pragma unroll
            for (int k = 0; k < Knod; k++) {
                float2 v = *(const float2*)&G[OAGG + k * 64 + 2 * lane];
                v.x = fmaxf(v.x + be.x, 0.f); v.y = fmaxf(v.y + be.y, 0.f);
                px += v.x; py += v.y;
                h2[k] = v;
                ssq[k] = v.x * v.x + v.y * v.y;
            }
#pragma unroll
            for (int st = 16; st > 0; st >>= 1)
#pragma unroll
                for (int k = 0; k < Knod; k++)
                    ssq[k] += __shfl_xor_sync(0xffffffffu, ssq[k], st);
#pragma unroll
            for (int k = 0; k < Knod; k++) {
                float inv = 1.f / fmaxf(sqrtf(ssq[k]), 1e-12f);
                float2 v = h2[k];
                v.x *= inv; v.y *= inv;
                *(float2*)&G[OAGG + k * 64 + 2 * lane] = v;
            }
        } else {
#pragma unroll
            for (int k = 0; k < Knod; k++) {
                float2 v = *(const float2*)&G[OAGG + k * 64 + 2 * lane];
                px += fmaxf(v.x + be.x, 0.f);
                py += fmaxf(v.y + be.y, 0.f);
            }
        }
        // pool l2n
        px *= (1.f / 16.f); py *= (1.f / 16.f);
        float pn = wred(px * px + py * py);
        float pinv = 1.f / fmaxf(sqrtf(pn), 1e-12f);
        G[OPOOL + s * 64 + 2 * lane]     = px * pinv;
        G[OPOOL + s * 64 + 2 * lane + 1] = py * pinv;

        if (s < 2) {
            // anchor = l2n(relu(Y[0] + b))
            float2 av = *(const float2*)&G[OY + 2 * lane];
            av.x = fmaxf(av.x + be.x, 0.f); av.y = fmaxf(av.y + be.y, 0.f);
            float an = wred(av.x * av.x + av.y * av.y);
            float ainv = 1.f / fmaxf(sqrtf(an), 1e-12f);
            G[OA + s * 64 + 2 * lane]     = av.x * ainv;
            G[OA + s * 64 + 2 * lane + 1] = av.y * ainv;

            // degrees: lanes 0-15 count src==lane; lanes 16-31 count dst==lane-16
            {
                const int target = lane & 15;
                const int* arr = (lane < 16) ? Gsrc : Gdst;
                int c = 0;
                for (int e = 0; e < Eedg; e++) c += (arr[e] == target);
                if (lane < 16) G[ODEG + lane] = (float)c;
                if (lane == 16) G[OSCAL + 4 + s] = rsqrtf(fmaxf((float)c, 1.f));  // nd (dst-node 0)
            }
            __syncwarp();

            // v gather over dst==0 edges (normalized h in place)
            float vx = 0.f, vy = 0.f;
            for (int e = 0; e < Eedg; e++) {
                if (Gdst[e] == 0) {
                    int se = Gsrc[e];
                    float rs = rsqrtf(fmaxf(G[ODEG + se], 1.f)) * Gwe[e];
                    float2 h2v = *(const float2*)&G[OAGG + se * 64 + 2 * lane];
                    vx = fmaf(rs, h2v.x, vx);
                    vy = fmaf(rs, h2v.y, vy);
                }
            }
            G[OV2 + 4 * lane + s]     = vx;   // feature 2*lane
            G[OV2 + 4 * lane + 2 + s] = vy;   // feature 2*lane+1
        }
        __syncwarp();
    }

    // discriminators
    {
        const float bb = __ldg(b_bil);
        for (int t = 0; t < 2; t++) {
            float u0 = 0.f, u1 = 0.f;
            const float* wr0 = sWb + lane * 65;
            const float* wr1 = sWb + (lane + 32) * 65;
#pragma unroll 8
            for (int k = 0; k < 64; k++) {
                float ak = G[OA + t * 64 + k];
                u0 = fmaf(wr0[k], ak, u0);
                u1 = fmaf(wr1[k], ak, u1);
            }
            float dp = wred(G[OPOOL + t * 64 + lane] * u0 + G[OPOOL + t * 64 + lane + 32] * u1);
            float dn = wred(G[OPOOL + 128 + lane] * u0 + G[OPOOL + 128 + lane + 32] * u1);
            if (lane == 0) {
                G[OSCAL + t]     = 1.f / (1.f + expf(-(dp + bb)));
                G[OSCAL + 2 + t] = 1.f / (1.f + expf(-(dn + bb)));
            }
        }
    }
    __syncthreads();

    // CTA-cooperative decoder: hd[g][dec][i] = relu((v @ W_dec)*nd + b_dec)
    for (int i = tid; i < FIN; i += 256) {
        uint64_t acc2[8];
#pragma unroll
        for (int q = 0; q < 8; q++) acc2[q] = 0ull;
#pragma unroll 8
        for (int f = 0; f < 64; f++) {
            uint64_t wb = bcast2(__ldg(&W_dec[f * FIN + i]));
#pragma unroll
            for (int q = 0; q < 8; q++)
                ffma2(acc2[q], wb, *(const uint64_t*)&sm[q * GSTR + OV2 + 2 * f]);
        }
        float bd = __ldg(&b_dec[i]);
#pragma unroll
        for (int q = 0; q < 8; q++) {
            float2 a = upk(acc2[q]);
            float nd0 = sm[q * GSTR + OSCAL + 4];
            float nd1 = sm[q * GSTR + OSCAL + 5];
            sm[q * GSTR + OAGG + i]       = fmaxf(a.x * nd0 + bd, 0.f);
            sm[q * GSTR + OAGG + 304 + i] = fmaxf(a.y * nd1 + bd, 0.f);
        }
    }
    __syncthreads();

    // per-warp epilogue: l2n + squared error vs original anchor features
    float s0 = 0.f, s1 = 0.f;
    for (int i = lane; i < FIN; i += 32) {
        float h0 = G[OAGG + i], h1 = G[OAGG + 304 + i];
        s0 = fmaf(h0, h0, s0);
        s1 = fmaf(h1, h1, s1);
    }
    s0 = wred(s0); s1 = wred(s1);
    float inv0 = 1.f / fmaxf(sqrtf(s0), 1e-12f);
    float inv1 = 1.f / fmaxf(sqrtf(s1), 1e-12f);

    const float* o0 = fp1 + (size_t)b * Knod * FIN;
    const float* o1 = fp2 + (size_t)b * Knod * FIN;
    float e0 = 0.f, e1 = 0.f;
    for (int i = lane; i < FIN; i += 32) {
        float d0 = G[OAGG + i] * inv0 - __ldg(&o0[i]);
        float d1 = G[OAGG + 304 + i] * inv1 - __ldg(&o1[i]);
        e0 = fmaf(d0, d0, e0);
        e1 = fmaf(d1, d1, e1);
    }
    e0 = wred(e0); e1 = wred(e1);

    if (lane == 0) {
        float ps1 = G[OSCAL + 0], ps2 = G[OSCAL + 1];
        float ns1 = G[OSCAL + 2], ns2 = G[OSCAL + 3];
        g_ssq1[b] = e0;
        g_ssq2[b] = e1;
        g_lt1[b] = logf(ps1) + logf(1.f - ns1);
        g_lt2[b] = logf(ps2) + logf(1.f - ns2);
        g_contr[b] = (ns1 - ps1 + 1.f) * 0.5f + (ns2 - ps2 + 1.f) * 0.5f;
    }
}

// ===========================================================================
__global__ void __launch_bounds__(256) finalize_kernel(float* out) {
    __shared__ float sR[256 * 4];
    int tid = threadIdx.x;
    float a = 0.f, c = 0.f, m1 = 0.f, m2 = 0.f;
    for (int i = tid; i < Bsz; i += 256) {
        a += g_ssq1[i]; c += g_ssq2[i];
        m1 += g_lt1[i]; m2 += g_lt2[i];
    }
    sR[tid] = a; sR[256 + tid] = c; sR[512 + tid] = m1; sR[768 + tid] = m2;
    __syncthreads();
    for (int s = 128; s > 0; s >>= 1) {
        if (tid < s) {
            sR[tid] += sR[tid + s];
            sR[256 + tid] += sR[256 + tid + s];
            sR[512 + tid] += sR[512 + tid + s];
            sR[768 + tid] += sR[768 + tid + s];
        }
        __syncthreads();
    }
    if (tid == 0) {
        float Ssq1 = sR[0], Ssq2 = sR[256], M1 = sR[512], M2 = sR[768];
        float L_con = -(M1 / (float)Bsz + M2 / (float)Bsz) * 0.25f;
        float L_gen = (Ssq1 + Ssq2) / (2.f * (float)Bsz * (float)FIN);
        out[0] = ALPHA * L_con + BETA * L_gen;
        g_gen = (sqrtf(Ssq1) + sqrtf(Ssq2)) / (2.f * sqrtf((float)FIN));
    }
}

__global__ void scores_kernel(float* out) {
    int i = blockIdx.x * blockDim.x + threadIdx.x;
    if (i < Bsz) out[1 + i] = ALPHA * g_contr[i] + BETA * g_gen;
}

// ===========================================================================
extern "C" void kernel_launch(void* const* d_in, const int* in_sizes, int n_in,
                              void* d_out, int out_size) {
    const float* feat_p1 = (const float*)d_in[0];
    const float* feat_p2 = (const float*)d_in[1];
    const float* feat_n  = (const float*)d_in[2];
    const float* w_p1    = (const float*)d_in[3];
    const float* w_p2    = (const float*)d_in[4];
    const float* w_n     = (const float*)d_in[5];
    const float* W_enc   = (const float*)d_in[6];
    const float* b_enc   = (const float*)d_in[7];
    const float* W_dec   = (const float*)d_in[8];
    const float* b_dec   = (const float*)d_in[9];
    const float* W_bil   = (const float*)d_in[10];
    const float* b_bil   = (const float*)d_in[11];
    const int* src_p1 = (const int*)d_in[12];
    const int* dst_p1 = (const int*)d_in[13];
    const int* src_p2 = (const int*)d_in[14];
    const int* dst_p2 = (const int*)d_in[15];
    const int* src_n  = (const int*)d_in[16];
    const int* dst_n  = (const int*)d_in[17];
    float* out = (float*)d_out;

    cudaFuncSetAttribute(gemm_kernel, cudaFuncAttributeMaxDynamicSharedMemorySize, GEMM_SMEM);
    cudaFuncSetAttribute(graph_kernel, cudaFuncAttributeMaxDynamicSharedMemorySize, GK_SMEM);

    gemm_kernel<<<GEMM_GRID, 256, GEMM_SMEM>>>(feat_p1, feat_p2, feat_n, W_enc);

    graph_kernel<<<Bsz / 8, 256, GK_SMEM>>>(
        feat_p1, feat_p2, w_p1, w_p2, w_n,
        b_enc, W_dec, b_dec, W_bil, b_bil,
        src_p1, dst_p1, src_p2, dst_p2, src_n, dst_n);

    finalize_kernel<<<1, 256>>>(out);
    scores_kernel<<<(Bsz + 255) / 256, 256>>>(out);
}

// round 7
// speedup vs baseline: 3.0755x; 1.7016x over previous
#include <cuda_runtime.h>
#include <cuda_bf16.h>
#include <math.h>
#include <stdint.h>

#define Bsz 8192
#define Knod 16
#define Eedg 64
#define FIN 300
#define FOUT 64
#define ALPHA 1.0f
#define BETA 0.6f

static __device__ float g_Y[(size_t)3 * Bsz * Knod * FOUT];   // ~100 MB scratch
static __device__ uint4 g_Wfrag[4864];                        // B fragments: hi [0,2432), lo [2432,4864)
static __device__ float g_ssq1[Bsz];
static __device__ float g_ssq2[Bsz];
static __device__ float g_lt1[Bsz];
static __device__ float g_lt2[Bsz];
static __device__ float g_contr[Bsz];

// ---------------- helpers ----------------
__device__ __forceinline__ uint32_t pk_bf2(float x, float y) {
    __nv_bfloat162 t = __floats2bfloat162_rn(x, y);   // .x (=x) in low 16 bits
    return *(uint32_t*)&t;
}
__device__ __forceinline__ float low_bf(uint32_t h)  { return __uint_as_float(h << 16); }
__device__ __forceinline__ float high_bf(uint32_t h) { return __uint_as_float(h & 0xffff0000u); }

__device__ __forceinline__ void mma16816(float* c, uint32_t a0, uint32_t a1, uint32_t a2, uint32_t a3,
                                         uint32_t b0, uint32_t b1) {
    asm volatile(
        "mma.sync.aligned.m16n8k16.row.col.f32.bf16.bf16.f32 "
        "{%0,%1,%2,%3}, {%4,%5,%6,%7}, {%8,%9}, {%0,%1,%2,%3};"
        : "+f"(c[0]), "+f"(c[1]), "+f"(c[2]), "+f"(c[3])
        : "r"(a0), "r"(a1), "r"(a2), "r"(a3), "r"(b0), "r"(b1));
}

__device__ __forceinline__ float2 upk(uint64_t v) {
    union { float2 f; uint64_t u; } c; c.u = v; return c.f;
}
__device__ __forceinline__ uint64_t bcast2(float x) {
    uint64_t r; uint32_t xi = __float_as_uint(x);
    asm("mov.b64 %0, {%1, %1};" : "=l"(r) : "r"(xi));
    return r;
}
__device__ __forceinline__ void ffma2(uint64_t& d, uint64_t a, uint64_t b) {
    asm("fma.rn.f32x2 %0, %1, %2, %0;" : "+l"(d) : "l"(a), "l"(b));
}
__device__ __forceinline__ float wred(float v) {
    v += __shfl_xor_sync(0xffffffffu, v, 16);
    v += __shfl_xor_sync(0xffffffffu, v, 8);
    v += __shfl_xor_sync(0xffffffffu, v, 4);
    v += __shfl_xor_sync(0xffffffffu, v, 2);
    v += __shfl_xor_sync(0xffffffffu, v, 1);
    return v;
}

// ===========================================================================
// Kernel 0: precompute W_enc fragments (bf16 hi/lo, HMMA m16n8k16 B layout)
// ===========================================================================
__global__ void prep_W(const float* __restrict__ W) {
    int idx = blockIdx.x * blockDim.x + threadIdx.x;   // 19*8*32 = 4864
    if (idx >= 4864) return;
    int lane = idx & 31, nt = (idx >> 5) & 7, kt = idx >> 8;
    int tig = lane & 3, grp = lane >> 2;
    int n = nt * 8 + grp;
    int k0 = kt * 16 + 2 * tig;
    float e0 = __ldg(&W[k0 * 64 + n]);                             // k0 <= 294
    float e1 = __ldg(&W[(k0 + 1) * 64 + n]);                       // <= 295
    float e2 = (k0 + 8 < FIN) ? __ldg(&W[(k0 + 8) * 64 + n]) : 0.f;
    float e3 = (k0 + 9 < FIN) ? __ldg(&W[(k0 + 9) * 64 + n]) : 0.f;

    uint32_t b0h = pk_bf2(e0, e1), b1h = pk_bf2(e2, e3);
    uint32_t b0l = pk_bf2(e0 - low_bf(b0h), e1 - high_bf(b0h));
    uint32_t b1l = pk_bf2(e2 - low_bf(b1h), e3 - high_bf(b1h));

    uint32_t* gw = (uint32_t*)g_Wfrag;
    int base = (((kt * 4) + (nt >> 1)) * 32 + lane) * 4 + (nt & 1) * 2;
    gw[base] = b0h;  gw[base + 1] = b1h;
    gw[9728 + base] = b0l;  gw[9728 + base + 1] = b1l;
}

// ===========================================================================
// Kernel 1: HMMA split-bf16 GEMM  Y = feat @ W_enc  (M=3*131072, K=300, N=64)
// warp = 16 rows x 64 cols; CTA = 128 rows; grid = 3072.
// ===========================================================================
#define GEMM_SMEM (4864 * 16)

__global__ void __launch_bounds__(256, 2) gemm_mma(
    const float* __restrict__ f1, const float* __restrict__ f2,
    const float* __restrict__ fn)
{
    extern __shared__ uint4 sB[];    // hi [0,2432), lo [2432,4864)
    const int tid = threadIdx.x;
    const int w = tid >> 5, lane = tid & 31;
    const int grp = lane >> 2, tig = lane & 3;

#pragma unroll
    for (int u = 0; u < 19; u++) sB[tid + 256 * u] = g_Wfrag[tid + 256 * u];
    __syncthreads();

    const int s = blockIdx.x >> 10, blk = blockIdx.x & 1023;
    const float* A = ((s == 0) ? f1 : (s == 1) ? f2 : fn) + (size_t)blk * 128 * FIN;
    const float* Ar0 = A + (size_t)(w * 16 + grp) * FIN;
    const float* Ar1 = Ar0 + 8 * FIN;

    float acc[8][4];
#pragma unroll
    for (int nt = 0; nt < 8; nt++)
#pragma unroll
        for (int q = 0; q < 4; q++) acc[nt][q] = 0.f;

#pragma unroll 1
    for (int kt = 0; kt < 19; kt++) {
        const int c0 = kt * 16 + 2 * tig;
        const int c1 = c0 + 8;
        float2 v00 = *(const float2*)(Ar0 + c0);
        float2 v10 = *(const float2*)(Ar1 + c0);
        float2 v01 = (c1 < FIN) ? *(const float2*)(Ar0 + c1) : make_float2(0.f, 0.f);
        float2 v11 = (c1 < FIN) ? *(const float2*)(Ar1 + c1) : make_float2(0.f, 0.f);

        uint32_t ah0 = pk_bf2(v00.x, v00.y);
        uint32_t ah1 = pk_bf2(v10.x, v10.y);
        uint32_t ah2 = pk_bf2(v01.x, v01.y);
        uint32_t ah3 = pk_bf2(v11.x, v11.y);
        uint32_t al0 = pk_bf2(v00.x - low_bf(ah0), v00.y - high_bf(ah0));
        uint32_t al1 = pk_bf2(v10.x - low_bf(ah1), v10.y - high_bf(ah1));
        uint32_t al2 = pk_bf2(v01.x - low_bf(ah2), v01.y - high_bf(ah2));
        uint32_t al3 = pk_bf2(v11.x - low_bf(ah3), v11.y - high_bf(ah3));

#pragma unroll
        for (int p = 0; p < 4; p++) {
            uint4 H = sB[(kt * 4 + p) * 32 + lane];
            uint4 L = sB[2432 + (kt * 4 + p) * 32 + lane];
            // hi * hi
            mma16816(acc[2 * p],     ah0, ah1, ah2, ah3, H.x, H.y);
            mma16816(acc[2 * p + 1], ah0, ah1, ah2, ah3, H.z, H.w);
            // hi * lo
            mma16816(acc[2 * p],     ah0, ah1, ah2, ah3, L.x, L.y);
            mma16816(acc[2 * p + 1], ah0, ah1, ah2, ah3, L.z, L.w);
            // lo * hi
            mma16816(acc[2 * p],     al0, al1, al2, al3, H.x, H.y);
            mma16816(acc[2 * p + 1], al0, al1, al2, al3, H.z, H.w);
        }
    }

    // epilogue: D[grp][2tig], D[grp][2tig+1], D[grp+8][2tig], D[grp+8][2tig+1]
    float* Yb = g_Y + ((size_t)s * (Bsz * Knod) + (size_t)blk * 128 + w * 16) * 64;
#pragma unroll
    for (int nt = 0; nt < 8; nt++) {
        int col = nt * 8 + 2 * tig;
        *(float2*)(Yb + (size_t)grp * 64 + col)       = make_float2(acc[nt][0], acc[nt][1]);
        *(float2*)(Yb + (size_t)(grp + 8) * 64 + col) = make_float2(acc[nt][2], acc[nt][3]);
    }
}

// ===========================================================================
// Kernel 2: warp-per-graph pipeline; 8 graphs/CTA; CTA-cooperative decoder.
// ===========================================================================
#define GSTR 2752
#define OY    0
#define OAGG  1024
#define OSRC  2048
#define ODST  2112
#define OWE   2176
#define OA    2240
#define OPOOL 2368
#define OV2   2560
#define OSCAL 2688
#define ODEG  2696
#define GK_SMEM ((8 * GSTR + 64 * 65) * 4)

__global__ void __launch_bounds__(256, 2) graph_kernel(
    const float* __restrict__ fp1, const float* __restrict__ fp2,
    const float* __restrict__ w_p1, const float* __restrict__ w_p2,
    const float* __restrict__ w_n,
    const float* __restrict__ b_enc, const float* __restrict__ W_dec,
    const float* __restrict__ b_dec, const float* __restrict__ W_bil,
    const float* __restrict__ b_bil,
    const int* __restrict__ sp1, const int* __restrict__ dp1,
    const int* __restrict__ sp2, const int* __restrict__ dp2,
    const int* __restrict__ spn, const int* __restrict__ dpn)
{
    extern __shared__ float sm[];
    float* sWb = sm + 8 * GSTR;
    const int tid = threadIdx.x, lane = tid & 31, g = tid >> 5;
    const int b = blockIdx.x * 8 + g;
    float* G = sm + g * GSTR;
    int* Gsrc = (int*)(G + OSRC);
    int* Gdst = (int*)(G + ODST);
    float* Gwe = G + OWE;

    for (int j = tid; j < 4096; j += 256)
        sWb[(j >> 6) * 65 + (j & 63)] = __ldg(&W_bil[j]);
    __syncthreads();

    const float2 be = *(const float2*)&b_enc[2 * lane];

    const int* srcs[3] = { sp1 + (long)b * Eedg, sp2 + (long)b * Eedg, spn + (long)b * Eedg };
    const int* dsts[3] = { dp1 + (long)b * Eedg, dp2 + (long)b * Eedg, dpn + (long)b * Eedg };
    const float* wgts[3] = { w_p1 + (long)b * Eedg, w_p2 + (long)b * Eedg, w_n + (long)b * Eedg };

    for (int s = 0; s < 3; s++) {
        Gsrc[lane] = __ldg(&srcs[s][lane]);  Gsrc[lane + 32] = __ldg(&srcs[s][lane + 32]);
        Gdst[lane] = __ldg(&dsts[s][lane]);  Gdst[lane + 32] = __ldg(&dsts[s][lane + 32]);
        Gwe[lane]  = __ldg(&wgts[s][lane]);  Gwe[lane + 32]  = __ldg(&wgts[s][lane + 32]);
        const float4* Yf4 = (const float4*)(g_Y + ((size_t)s * (Bsz * Knod) + (size_t)b * Knod) * 64);
#pragma unroll
        for (int u = 0; u < 8; u++)
            *(float4*)&G[OY + 4 * (lane + 32 * u)] = __ldg(&Yf4[lane + 32 * u]);
#pragma unroll
        for (int k = 0; k < Knod; k++)
            *(float2*)&G[OAGG + k * 64 + 2 * lane] = make_float2(0.f, 0.f);
        __syncwarp();

        for (int e = 0; e < Eedg; e++) {
            int se = Gsrc[e];
            if (se != 0) {
                int de = Gdst[e]; float w = Gwe[e];
                float2 y = *(const float2*)&G[OY + se * 64 + 2 * lane];
                float2* ap = (float2*)&G[OAGG + de * 64 + 2 * lane];
                float2 a = *ap;
                a.x = fmaf(w, y.x, a.x); a.y = fmaf(w, y.y, a.y);
                *ap = a;
            }
        }

        float px = 0.f, py = 0.f;
        if (s < 2) {
            float2 h2[Knod];
            float ssq[Knod];
#pragma unroll
            for (int k = 0; k < Knod; k++) {
                float2 v = *(const float2*)&G[OAGG + k * 64 + 2 * lane];
                v.x = fmaxf(v.x + be.x, 0.f); v.y = fmaxf(v.y + be.y, 0.f);
                px += v.x; py += v.y;
                h2[k] = v;
                ssq[k] = v.x * v.x + v.y * v.y;
            }
#pragma unroll
            for (int st = 16; st > 0; st >>= 1)
#pragma unroll
                for (int k = 0; k < Knod; k++)
                    ssq[k] += __shfl_xor_sync(0xffffffffu, ssq[k], st);
#pragma unroll
            for (int k = 0; k < Knod; k++) {
                float inv = 1.f / fmaxf(sqrtf(ssq[k]), 1e-12f);
                float2 v = h2[k];
                v.x *= inv; v.y *= inv;
                *(float2*)&G[OAGG + k * 64 + 2 * lane] = v;
            }
        } else {
#pragma unroll
            for (int k = 0; k < Knod; k++) {
                float2 v = *(const float2*)&G[OAGG + k * 64 + 2 * lane];
                px += fmaxf(v.x + be.x, 0.f);
                py += fmaxf(v.y + be.y, 0.f);
            }
        }
        px *= (1.f / 16.f); py *= (1.f / 16.f);
        float pn = wred(px * px + py * py);
        float pinv = 1.f / fmaxf(sqrtf(pn), 1e-12f);
        G[OPOOL + s * 64 + 2 * lane]     = px * pinv;
        G[OPOOL + s * 64 + 2 * lane + 1] = py * pinv;

        if (s < 2) {
            float2 av = *(const float2*)&G[OY + 2 * lane];
            av.x = fmaxf(av.x + be.x, 0.f); av.y = fmaxf(av.y + be.y, 0.f);
            float an = wred(av.x * av.x + av.y * av.y);
            float ainv = 1.f / fmaxf(sqrtf(an), 1e-12f);
            G[OA + s * 64 + 2 * lane]     = av.x * ainv;
            G[OA + s * 64 + 2 * lane + 1] = av.y * ainv;

            {
                const int target = lane & 15;
                const int* arr = (lane < 16) ? Gsrc : Gdst;
                int c = 0;
                for (int e = 0; e < Eedg; e++) c += (arr[e] == target);
                if (lane < 16) G[ODEG + lane] = (float)c;
                if (lane == 16) G[OSCAL + 4 + s] = rsqrtf(fmaxf((float)c, 1.f));
            }
            __syncwarp();

            float vx = 0.f, vy = 0.f;
            for (int e = 0; e < Eedg; e++) {
                if (Gdst[e] == 0) {
                    int se = Gsrc[e];
                    float rs = rsqrtf(fmaxf(G[ODEG + se], 1.f)) * Gwe[e];
                    float2 h2v = *(const float2*)&G[OAGG + se * 64 + 2 * lane];
                    vx = fmaf(rs, h2v.x, vx);
                    vy = fmaf(rs, h2v.y, vy);
                }
            }
            G[OV2 + 4 * lane + s]     = vx;
            G[OV2 + 4 * lane + 2 + s] = vy;
        }
        __syncwarp();
    }

    {
        const float bb = __ldg(b_bil);
        for (int t = 0; t < 2; t++) {
            float u0 = 0.f, u1 = 0.f;
            const float* wr0 = sWb + lane * 65;
            const float* wr1 = sWb + (lane + 32) * 65;
#pragma unroll 8
            for (int k = 0; k < 64; k++) {
                float ak = G[OA + t * 64 + k];
                u0 = fmaf(wr0[k], ak, u0);
                u1 = fmaf(wr1[k], ak, u1);
            }
            float dp = wred(G[OPOOL + t * 64 + lane] * u0 + G[OPOOL + t * 64 + lane + 32] * u1);
            float dn = wred(G[OPOOL + 128 + lane] * u0 + G[OPOOL + 128 + lane + 32] * u1);
            if (lane == 0) {
                G[OSCAL + t]     = 1.f / (1.f + expf(-(dp + bb)));
                G[OSCAL + 2 + t] = 1.f / (1.f + expf(-(dn + bb)));
            }
        }
    }
    __syncthreads();

    for (int i = tid; i < FIN; i += 256) {
        uint64_t acc2[8];
#pragma unroll
        for (int q = 0; q < 8; q++) acc2[q] = 0ull;
#pragma unroll 8
        for (int f = 0; f < 64; f++) {
            uint64_t wb = bcast2(__ldg(&W_dec[f * FIN + i]));
#pragma unroll
            for (int q = 0; q < 8; q++)
                ffma2(acc2[q], wb, *(const uint64_t*)&sm[q * GSTR + OV2 + 2 * f]);
        }
        float bd = __ldg(&b_dec[i]);
#pragma unroll
        for (int q = 0; q < 8; q++) {
            float2 a = upk(acc2[q]);
            float nd0 = sm[q * GSTR + OSCAL + 4];
            float nd1 = sm[q * GSTR + OSCAL + 5];
            sm[q * GSTR + OAGG + i]       = fmaxf(a.x * nd0 + bd, 0.f);
            sm[q * GSTR + OAGG + 304 + i] = fmaxf(a.y * nd1 + bd, 0.f);
        }
    }
    __syncthreads();

    float s0 = 0.f, s1 = 0.f;
    for (int i = lane; i < FIN; i += 32) {
        float h0 = G[OAGG + i], h1 = G[OAGG + 304 + i];
        s0 = fmaf(h0, h0, s0);
        s1 = fmaf(h1, h1, s1);
    }
    s0 = wred(s0); s1 = wred(s1);
    float inv0 = 1.f / fmaxf(sqrtf(s0), 1e-12f);
    float inv1 = 1.f / fmaxf(sqrtf(s1), 1e-12f);

    const float* o0 = fp1 + (size_t)b * Knod * FIN;
    const float* o1 = fp2 + (size_t)b * Knod * FIN;
    float e0 = 0.f, e1 = 0.f;
    for (int i = lane; i < FIN; i += 32) {
        float d0 = G[OAGG + i] * inv0 - __ldg(&o0[i]);
        float d1 = G[OAGG + 304 + i] * inv1 - __ldg(&o1[i]);
        e0 = fmaf(d0, d0, e0);
        e1 = fmaf(d1, d1, e1);
    }
    e0 = wred(e0); e1 = wred(e1);

    if (lane == 0) {
        float ps1 = G[OSCAL + 0], ps2 = G[OSCAL + 1];
        float ns1 = G[OSCAL + 2], ns2 = G[OSCAL + 3];
        g_ssq1[b] = e0;
        g_ssq2[b] = e1;
        g_lt1[b] = logf(ps1) + logf(1.f - ns1);
        g_lt2[b] = logf(ps2) + logf(1.f - ns2);
        g_contr[b] = (ns1 - ps1 + 1.f) * 0.5f + (ns2 - ps2 + 1.f) * 0.5f;
    }
}

// ===========================================================================
// Kernel 3: finalize -> L (out[0]), then scores out[1..Bsz]
// ===========================================================================
__global__ void __launch_bounds__(256) finalize_kernel(float* out) {
    __shared__ float sR[256 * 4];
    __shared__ float sGen;
    int tid = threadIdx.x;
    float a = 0.f, c = 0.f, m1 = 0.f, m2 = 0.f;
    for (int i = tid; i < Bsz; i += 256) {
        a += g_ssq1[i]; c += g_ssq2[i];
        m1 += g_lt1[i]; m2 += g_lt2[i];
    }
    sR[tid] = a; sR[256 + tid] = c; sR[512 + tid] = m1; sR[768 + tid] = m2;
    __syncthreads();
    for (int s = 128; s > 0; s >>= 1) {
        if (tid < s) {
            sR[tid] += sR[tid + s];
            sR[256 + tid] += sR[256 + tid + s];
            sR[512 + tid] += sR[512 + tid + s];
            sR[768 + tid] += sR[768 + tid + s];
        }
        __syncthreads();
    }
    if (tid == 0) {
        float Ssq1 = sR[0], Ssq2 = sR[256], M1 = sR[512], M2 = sR[768];
        float L_con = -(M1 / (float)Bsz + M2 / (float)Bsz) * 0.25f;
        float L_gen = (Ssq1 + Ssq2) / (2.f * (float)Bsz * (float)FIN);
        out[0] = ALPHA * L_con + BETA * L_gen;
        sGen = (sqrtf(Ssq1) + sqrtf(Ssq2)) / (2.f * sqrtf((float)FIN));
    }
    __syncthreads();
    float gen = sGen;
    for (int i = tid; i < Bsz; i += 256)
        out[1 + i] = ALPHA * g_contr[i] + BETA * gen;
}

// ===========================================================================
extern "C" void kernel_launch(void* const* d_in, const int* in_sizes, int n_in,
                              void* d_out, int out_size) {
    const float* feat_p1 = (const float*)d_in[0];
    const float* feat_p2 = (const float*)d_in[1];
    const float* feat_n  = (const float*)d_in[2];
    const float* w_p1    = (const float*)d_in[3];
    const float* w_p2    = (const float*)d_in[4];
    const float* w_n     = (const float*)d_in[5];
    const float* W_enc   = (const float*)d_in[6];
    const float* b_enc   = (const float*)d_in[7];
    const float* W_dec   = (const float*)d_in[8];
    const float* b_dec   = (const float*)d_in[9];
    const float* W_bil   = (const float*)d_in[10];
    const float* b_bil   = (const float*)d_in[11];
    const int* src_p1 = (const int*)d_in[12];
    const int* dst_p1 = (const int*)d_in[13];
    const int* src_p2 = (const int*)d_in[14];
    const int* dst_p2 = (const int*)d_in[15];
    const int* src_n  = (const int*)d_in[16];
    const int* dst_n  = (const int*)d_in[17];
    float* out = (float*)d_out;

    cudaFuncSetAttribute(gemm_mma, cudaFuncAttributeMaxDynamicSharedMemorySize, GEMM_SMEM);
    cudaFuncSetAttribute(graph_kernel, cudaFuncAttributeMaxDynamicSharedMemorySize, GK_SMEM);

    prep_W<<<19, 256>>>(W_enc);
    gemm_mma<<<3072, 256, GEMM_SMEM>>>(feat_p1, feat_p2, feat_n);

    graph_kernel<<<Bsz / 8, 256, GK_SMEM>>>(
        feat_p1, feat_p2, w_p1, w_p2, w_n,
        b_enc, W_dec, b_dec, W_bil, b_bil,
        src_p1, dst_p1, src_p2, dst_p2, src_n, dst_n);

    finalize_kernel<<<1, 256>>>(out);
}

// round 10
// speedup vs baseline: 3.4112x; 1.1092x over previous
#include <cuda_runtime.h>
#include <cuda_bf16.h>
#include <math.h>
#include <stdint.h>

#define Bsz 8192
#define Knod 16
#define Eedg 64
#define FIN 300
#define FOUT 64
#define ALPHA 1.0f
#define BETA 0.6f

static __device__ float g_Y[(size_t)3 * Bsz * Knod * FOUT];   // ~100 MB scratch
static __device__ uint4 g_Wfrag[4864];     // encoder B frags: hi [0,2432), lo [2432,4864)
static __device__ uint4 g_WdF[4864];       // decoder B frags: hi [0,2432), lo [2432,4864)
static __device__ float g_V[(size_t)2 * Bsz * FOUT];          // decoder inputs, row = 2b+dec
static __device__ float g_nd[2 * Bsz];
static __device__ float g_lt1[Bsz];
static __device__ float g_lt2[Bsz];
static __device__ float g_contr[Bsz];
static __device__ float g_part[128 * 4];
static __device__ float g_gen;

// ---------------- helpers ----------------
__device__ __forceinline__ uint32_t pk_bf2(float x, float y) {
    __nv_bfloat162 t = __floats2bfloat162_rn(x, y);   // x in low 16 bits
    return *(uint32_t*)&t;
}
__device__ __forceinline__ float low_bf(uint32_t h)  { return __uint_as_float(h << 16); }
__device__ __forceinline__ float high_bf(uint32_t h) { return __uint_as_float(h & 0xffff0000u); }

__device__ __forceinline__ void mma16816(float* c, uint32_t a0, uint32_t a1, uint32_t a2, uint32_t a3,
                                         uint32_t b0, uint32_t b1) {
    asm volatile(
        "mma.sync.aligned.m16n8k16.row.col.f32.bf16.bf16.f32 "
        "{%0,%1,%2,%3}, {%4,%5,%6,%7}, {%8,%9}, {%0,%1,%2,%3};"
        : "+f"(c[0]), "+f"(c[1]), "+f"(c[2]), "+f"(c[3])
        : "r"(a0), "r"(a1), "r"(a2), "r"(a3), "r"(b0), "r"(b1));
}
__device__ __forceinline__ float wred(float v) {
    v += __shfl_xor_sync(0xffffffffu, v, 16);
    v += __shfl_xor_sync(0xffffffffu, v, 8);
    v += __shfl_xor_sync(0xffffffffu, v, 4);
    v += __shfl_xor_sync(0xffffffffu, v, 2);
    v += __shfl_xor_sync(0xffffffffu, v, 1);
    return v;
}
__device__ __forceinline__ float bsum(float v, float* sR) {
    int tid = threadIdx.x;
    sR[tid] = v;
    __syncthreads();
#pragma unroll
    for (int s = 128; s > 0; s >>= 1) {
        if (tid < s && tid + s < 256) sR[tid] += sR[tid + s];
        __syncthreads();
    }
    float r = sR[0];
    __syncthreads();
    return r;
}

// ===========================================================================
// Kernel 0: precompute W_enc + W_dec fragments (bf16 hi/lo, HMMA B layout)
// ===========================================================================
__global__ void prep_W(const float* __restrict__ W_enc, const float* __restrict__ W_dec) {
    int idx = blockIdx.x * blockDim.x + threadIdx.x;
    if (idx < 4864) {
        // encoder: B = W_enc [k=300pad304][n=64]; kt 0..18, nt 0..7
        int lane = idx & 31, nt = (idx >> 5) & 7, kt = idx >> 8;
        int tig = lane & 3, grp = lane >> 2;
        int n = nt * 8 + grp;
        int k0 = kt * 16 + 2 * tig;
        float e0 = __ldg(&W_enc[k0 * 64 + n]);
        float e1 = __ldg(&W_enc[(k0 + 1) * 64 + n]);
        float e2 = (k0 + 8 < FIN) ? __ldg(&W_enc[(k0 + 8) * 64 + n]) : 0.f;
        float e3 = (k0 + 9 < FIN) ? __ldg(&W_enc[(k0 + 9) * 64 + n]) : 0.f;
        uint32_t b0h = pk_bf2(e0, e1), b1h = pk_bf2(e2, e3);
        uint32_t b0l = pk_bf2(e0 - low_bf(b0h), e1 - high_bf(b0h));
        uint32_t b1l = pk_bf2(e2 - low_bf(b1h), e3 - high_bf(b1h));
        uint32_t* gw = (uint32_t*)g_Wfrag;
        int base = (((kt * 4) + (nt >> 1)) * 32 + lane) * 4 + (nt & 1) * 2;
        gw[base] = b0h;  gw[base + 1] = b1h;
        gw[9728 + base] = b0l;  gw[9728 + base + 1] = b1l;
    } else {
        int i2 = idx - 4864;
        if (i2 >= 4864) return;
        // decoder: B = W_dec [k=64][n=300pad304]; kt 0..3, nt 0..37
        int lane = i2 & 31, kt = (i2 >> 5) & 3, nt = i2 >> 7;
        int tig = lane & 3, grp = lane >> 2;
        int n = nt * 8 + grp;
        int k0 = kt * 16 + 2 * tig;
        float e0 = 0.f, e1 = 0.f, e2 = 0.f, e3 = 0.f;
        if (n < FIN) {
            e0 = __ldg(&W_dec[k0 * FIN + n]);
            e1 = __ldg(&W_dec[(k0 + 1) * FIN + n]);
            e2 = __ldg(&W_dec[(k0 + 8) * FIN + n]);
            e3 = __ldg(&W_dec[(k0 + 9) * FIN + n]);
        }
        uint32_t b0h = pk_bf2(e0, e1), b1h = pk_bf2(e2, e3);
        uint32_t b0l = pk_bf2(e0 - low_bf(b0h), e1 - high_bf(b0h));
        uint32_t b1l = pk_bf2(e2 - low_bf(b1h), e3 - high_bf(b1h));
        uint32_t* gw = (uint32_t*)g_WdF;
        int base = (((nt >> 1) * 4 + kt) * 32 + lane) * 4 + (nt & 1) * 2;
        gw[base] = b0h;  gw[base + 1] = b1h;
        gw[9728 + base] = b0l;  gw[9728 + base + 1] = b1l;
    }
}

// ===========================================================================
// Kernel 1: HMMA split-bf16 GEMM  Y = feat @ W_enc  (prefetch-pipelined)
// ===========================================================================
#define GEMM_SMEM (4864 * 16)

__global__ void __launch_bounds__(256, 2) gemm_mma(
    const float* __restrict__ f1, const float* __restrict__ f2,
    const float* __restrict__ fn)
{
    extern __shared__ uint4 sB[];    // hi [0,2432), lo [2432,4864)
    const int tid = threadIdx.x;
    const int w = tid >> 5, lane = tid & 31;
    const int grp = lane >> 2, tig = lane & 3;

#pragma unroll
    for (int u = 0; u < 19; u++) sB[tid + 256 * u] = g_Wfrag[tid + 256 * u];
    __syncthreads();

    const int s = blockIdx.x >> 10, blk = blockIdx.x & 1023;
    const float* A = ((s == 0) ? f1 : (s == 1) ? f2 : fn) + (size_t)blk * 128 * FIN;
    const float* Ar0 = A + (size_t)(w * 16 + grp) * FIN;
    const float* Ar1 = Ar0 + 8 * FIN;

    float acc[8][4];
#pragma unroll
    for (int nt = 0; nt < 8; nt++)
#pragma unroll
        for (int q = 0; q < 4; q++) acc[nt][q] = 0.f;

    // prologue loads (kt = 0)
    float2 v00, v10, v01, v11;
    {
        const int c0 = 2 * tig, c1 = c0 + 8;
        v00 = *(const float2*)(Ar0 + c0);
        v10 = *(const float2*)(Ar1 + c0);
        v01 = *(const float2*)(Ar0 + c1);
        v11 = *(const float2*)(Ar1 + c1);
    }

#pragma unroll 1
    for (int kt = 0; kt < 19; kt++) {
        uint32_t ah0 = pk_bf2(v00.x, v00.y);
        uint32_t ah1 = pk_bf2(v10.x, v10.y);
        uint32_t ah2 = pk_bf2(v01.x, v01.y);
        uint32_t ah3 = pk_bf2(v11.x, v11.y);
        uint32_t al0 = pk_bf2(v00.x - low_bf(ah0), v00.y - high_bf(ah0));
        uint32_t al1 = pk_bf2(v10.x - low_bf(ah1), v10.y - high_bf(ah1));
        uint32_t al2 = pk_bf2(v01.x - low_bf(ah2), v01.y - high_bf(ah2));
        uint32_t al3 = pk_bf2(v11.x - low_bf(ah3), v11.y - high_bf(ah3));

        // prefetch next k-tile while MMAs run
        float2 t00, t10, t01, t11;
        if (kt < 18) {
            const int c0 = (kt + 1) * 16 + 2 * tig;
            const int c1 = c0 + 8;
            t00 = *(const float2*)(Ar0 + c0);
            t10 = *(const float2*)(Ar1 + c0);
            t01 = (c1 < FIN) ? *(const float2*)(Ar0 + c1) : make_float2(0.f, 0.f);
            t11 = (c1 < FIN) ? *(const float2*)(Ar1 + c1) : make_float2(0.f, 0.f);
        } else {
            t00 = v00; t10 = v10; t01 = v01; t11 = v11;
        }

#pragma unroll
        for (int p = 0; p < 4; p++) {
            uint4 H = sB[(kt * 4 + p) * 32 + lane];
            uint4 L = sB[2432 + (kt * 4 + p) * 32 + lane];
            mma16816(acc[2 * p],     ah0, ah1, ah2, ah3, H.x, H.y);
            mma16816(acc[2 * p + 1], ah0, ah1, ah2, ah3, H.z, H.w);
            mma16816(acc[2 * p],     ah0, ah1, ah2, ah3, L.x, L.y);
            mma16816(acc[2 * p + 1], ah0, ah1, ah2, ah3, L.z, L.w);
            mma16816(acc[2 * p],     al0, al1, al2, al3, H.x, H.y);
            mma16816(acc[2 * p + 1], al0, al1, al2, al3, H.z, H.w);
        }
        v00 = t00; v10 = t10; v01 = t01; v11 = t11;
    }

    float* Yb = g_Y + ((size_t)s * (Bsz * Knod) + (size_t)blk * 128 + w * 16) * 64;
#pragma unroll
    for (int nt = 0; nt < 8; nt++) {
        int col = nt * 8 + 2 * tig;
        *(float2*)(Yb + (size_t)grp * 64 + col)       = make_float2(acc[nt][0], acc[nt][1]);
        *(float2*)(Yb + (size_t)(grp + 8) * 64 + col) = make_float2(acc[nt][2], acc[nt][3]);
    }
}

// ===========================================================================
// Kernel 2: warp-per-graph encoder/SpMM/disc pipeline (decoder moved out).
// ===========================================================================
#define GSTR 2752
#define OY    0
#define OAGG  1024
#define OSRC  2048
#define ODST  2112
#define OWE   2176
#define OA    2240
#define OPOOL 2368
#define OSCAL 2688
#define ODEG  2696
#define GK_SMEM ((8 * GSTR + 64 * 65) * 4)

__global__ void __launch_bounds__(256, 2) graph_kernel(
    const float* __restrict__ w_p1, const float* __restrict__ w_p2,
    const float* __restrict__ w_n,
    const float* __restrict__ b_enc, const float* __restrict__ W_bil,
    const float* __restrict__ b_bil,
    const int* __restrict__ sp1, const int* __restrict__ dp1,
    const int* __restrict__ sp2, const int* __restrict__ dp2,
    const int* __restrict__ spn, const int* __restrict__ dpn)
{
    extern __shared__ float sm[];
    float* sWb = sm + 8 * GSTR;
    const int tid = threadIdx.x, lane = tid & 31, g = tid >> 5;
    const int b = blockIdx.x * 8 + g;
    float* G = sm + g * GSTR;
    int* Gsrc = (int*)(G + OSRC);
    int* Gdst = (int*)(G + ODST);
    float* Gwe = G + OWE;

    for (int j = tid; j < 4096; j += 256)
        sWb[(j >> 6) * 65 + (j & 63)] = __ldg(&W_bil[j]);
    __syncthreads();

    const float2 be = *(const float2*)&b_enc[2 * lane];

    const int* srcs[3] = { sp1 + (long)b * Eedg, sp2 + (long)b * Eedg, spn + (long)b * Eedg };
    const int* dsts[3] = { dp1 + (long)b * Eedg, dp2 + (long)b * Eedg, dpn + (long)b * Eedg };
    const float* wgts[3] = { w_p1 + (long)b * Eedg, w_p2 + (long)b * Eedg, w_n + (long)b * Eedg };

    for (int s = 0; s < 3; s++) {
        Gsrc[lane] = __ldg(&srcs[s][lane]);  Gsrc[lane + 32] = __ldg(&srcs[s][lane + 32]);
        Gdst[lane] = __ldg(&dsts[s][lane]);  Gdst[lane + 32] = __ldg(&dsts[s][lane + 32]);
        Gwe[lane]  = __ldg(&wgts[s][lane]);  Gwe[lane + 32]  = __ldg(&wgts[s][lane + 32]);
        const float4* Yf4 = (const float4*)(g_Y + ((size_t)s * (Bsz * Knod) + (size_t)b * Knod) * 64);
#pragma unroll
        for (int u = 0; u < 8; u++)
            *(float4*)&G[OY + 4 * (lane + 32 * u)] = __ldg(&Yf4[lane + 32 * u]);
#pragma unroll
        for (int k = 0; k < Knod; k++)
            *(float2*)&G[OAGG + k * 64 + 2 * lane] = make_float2(0.f, 0.f);
        __syncwarp();

        // SpMM (x row 0 is zero in encoder -> skip src==0)
        for (int e = 0; e < Eedg; e++) {
            int se = Gsrc[e];
            if (se != 0) {
                int de = Gdst[e]; float w = Gwe[e];
                float2 y = *(const float2*)&G[OY + se * 64 + 2 * lane];
                float2* ap = (float2*)&G[OAGG + de * 64 + 2 * lane];
                float2 a = *ap;
                a.x = fmaf(w, y.x, a.x); a.y = fmaf(w, y.y, a.y);
                *ap = a;
            }
        }

        float px = 0.f, py = 0.f;
        if (s < 2) {
            float2 h2[Knod];
            float ssq[Knod];
#pragma unroll
            for (int k = 0; k < Knod; k++) {
                float2 v = *(const float2*)&G[OAGG + k * 64 + 2 * lane];
                v.x = fmaxf(v.x + be.x, 0.f); v.y = fmaxf(v.y + be.y, 0.f);
                px += v.x; py += v.y;
                h2[k] = v;
                ssq[k] = v.x * v.x + v.y * v.y;
            }
#pragma unroll
            for (int st = 16; st > 0; st >>= 1)
#pragma unroll
                for (int k = 0; k < Knod; k++)
                    ssq[k] += __shfl_xor_sync(0xffffffffu, ssq[k], st);
#pragma unroll
            for (int k = 0; k < Knod; k++) {
                float inv = 1.f / fmaxf(sqrtf(ssq[k]), 1e-12f);
                float2 v = h2[k];
                v.x *= inv; v.y *= inv;
                *(float2*)&G[OAGG + k * 64 + 2 * lane] = v;
            }
        } else {
#pragma unroll
            for (int k = 0; k < Knod; k++) {
                float2 v = *(const float2*)&G[OAGG + k * 64 + 2 * lane];
                px += fmaxf(v.x + be.x, 0.f);
                py += fmaxf(v.y + be.y, 0.f);
            }
        }
        px *= (1.f / 16.f); py *= (1.f / 16.f);
        float pn = wred(px * px + py * py);
        float pinv = 1.f / fmaxf(sqrtf(pn), 1e-12f);
        G[OPOOL + s * 64 + 2 * lane]     = px * pinv;
        G[OPOOL + s * 64 + 2 * lane + 1] = py * pinv;

        if (s < 2) {
            float2 av = *(const float2*)&G[OY + 2 * lane];
            av.x = fmaxf(av.x + be.x, 0.f); av.y = fmaxf(av.y + be.y, 0.f);
            float an = wred(av.x * av.x + av.y * av.y);
            float ainv = 1.f / fmaxf(sqrtf(an), 1e-12f);
            G[OA + s * 64 + 2 * lane]     = av.x * ainv;
            G[OA + s * 64 + 2 * lane + 1] = av.y * ainv;

            {
                const int target = lane & 15;
                const int* arr = (lane < 16) ? Gsrc : Gdst;
                int c = 0;
                for (int e = 0; e < Eedg; e++) c += (arr[e] == target);
                if (lane < 16) G[ODEG + lane] = (float)c;
                if (lane == 16) g_nd[2 * b + s] = rsqrtf(fmaxf((float)c, 1.f));
            }
            __syncwarp();

            float vx = 0.f, vy = 0.f;
            for (int e = 0; e < Eedg; e++) {
                if (Gdst[e] == 0) {
                    int se = Gsrc[e];
                    float rs = rsqrtf(fmaxf(G[ODEG + se], 1.f)) * Gwe[e];
                    float2 h2v = *(const float2*)&G[OAGG + se * 64 + 2 * lane];
                    vx = fmaf(rs, h2v.x, vx);
                    vy = fmaf(rs, h2v.y, vy);
                }
            }
            *(float2*)&g_V[(size_t)(2 * b + s) * 64 + 2 * lane] = make_float2(vx, vy);
        }
        __syncwarp();
    }

    // discriminators
    {
        const float bb = __ldg(b_bil);
        for (int t = 0; t < 2; t++) {
            float u0 = 0.f, u1 = 0.f;
            const float* wr0 = sWb + lane * 65;
            const float* wr1 = sWb + (lane + 32) * 65;
#pragma unroll 8
            for (int k = 0; k < 64; k++) {
                float ak = G[OA + t * 64 + k];
                u0 = fmaf(wr0[k], ak, u0);
                u1 = fmaf(wr1[k], ak, u1);
            }
            float dp = wred(G[OPOOL + t * 64 + lane] * u0 + G[OPOOL + t * 64 + lane + 32] * u1);
            float dn = wred(G[OPOOL + 128 + lane] * u0 + G[OPOOL + 128 + lane + 32] * u1);
            if (lane == 0) {
                G[OSCAL + t]     = 1.f / (1.f + expf(-(dp + bb)));
                G[OSCAL + 2 + t] = 1.f / (1.f + expf(-(dn + bb)));
            }
        }
    }
    __syncwarp();

    if (lane == 0) {
        float ps1 = G[OSCAL + 0], ps2 = G[OSCAL + 1];
        float ns1 = G[OSCAL + 2], ns2 = G[OSCAL + 3];
        g_lt1[b] = logf(ps1) + logf(1.f - ns1);
        g_lt2[b] = logf(ps2) + logf(1.f - ns2);
        g_contr[b] = (ns1 - ps1 + 1.f) * 0.5f + (ns2 - ps2 + 1.f) * 0.5f;
    }
}

// ===========================================================================
// Kernel 3: HMMA decoder + fused error. 128 CTAs x 256 thr; warp = 16 rows.
// Row r = 2*graph + dec. hd never materialized: e = ssq*inv^2 - 2*inv*dot + osq.
// ===========================================================================
__global__ void __launch_bounds__(256) dec_err(
    const float* __restrict__ fp1, const float* __restrict__ fp2,
    const float* __restrict__ b_dec)
{
    __shared__ float sErow[128];
    __shared__ float sR[256];
    const int tid = threadIdx.x;
    const int w = tid >> 5, lane = tid & 31;
    const int grp = lane >> 2, tig = lane & 3;
    const int base = blockIdx.x * 128 + w * 16;
    const int r0 = base + grp, r1 = r0 + 8;

    // A fragments from V rows (split bf16)
    uint32_t ah[4][4], al[4][4];
#pragma unroll
    for (int kt = 0; kt < 4; kt++) {
        const int k0 = kt * 16 + 2 * tig;
        float2 x00 = *(const float2*)&g_V[(size_t)r0 * 64 + k0];
        float2 x10 = *(const float2*)&g_V[(size_t)r1 * 64 + k0];
        float2 x01 = *(const float2*)&g_V[(size_t)r0 * 64 + k0 + 8];
        float2 x11 = *(const float2*)&g_V[(size_t)r1 * 64 + k0 + 8];
        ah[kt][0] = pk_bf2(x00.x, x00.y);
        ah[kt][1] = pk_bf2(x10.x, x10.y);
        ah[kt][2] = pk_bf2(x01.x, x01.y);
        ah[kt][3] = pk_bf2(x11.x, x11.y);
        al[kt][0] = pk_bf2(x00.x - low_bf(ah[kt][0]), x00.y - high_bf(ah[kt][0]));
        al[kt][1] = pk_bf2(x10.x - low_bf(ah[kt][1]), x10.y - high_bf(ah[kt][1]));
        al[kt][2] = pk_bf2(x01.x - low_bf(ah[kt][2]), x01.y - high_bf(ah[kt][2]));
        al[kt][3] = pk_bf2(x11.x - low_bf(ah[kt][3]), x11.y - high_bf(ah[kt][3]));
    }
    const float nd0 = g_nd[r0], nd1 = g_nd[r1];
    const float* ori0 = ((r0 & 1) ? fp2 : fp1) + (size_t)(r0 >> 1) * (Knod * FIN);
    const float* ori1 = ((r1 & 1) ? fp2 : fp1) + (size_t)(r1 >> 1) * (Knod * FIN);

    float shh0 = 0.f, sho0 = 0.f, soo0 = 0.f;
    float shh1 = 0.f, sho1 = 0.f, soo1 = 0.f;

#pragma unroll 1
    for (int ntp = 0; ntp < 19; ntp++) {
        float acc0[4] = {0.f, 0.f, 0.f, 0.f};
        float acc1[4] = {0.f, 0.f, 0.f, 0.f};
#pragma unroll
        for (int kt = 0; kt < 4; kt++) {
            uint4 H = __ldg(&g_WdF[(ntp * 4 + kt) * 32 + lane]);
            uint4 L = __ldg(&g_WdF[2432 + (ntp * 4 + kt) * 32 + lane]);
            mma16816(acc0, ah[kt][0], ah[kt][1], ah[kt][2], ah[kt][3], H.x, H.y);
            mma16816(acc1, ah[kt][0], ah[kt][1], ah[kt][2], ah[kt][3], H.z, H.w);
            mma16816(acc0, ah[kt][0], ah[kt][1], ah[kt][2], ah[kt][3], L.x, L.y);
            mma16816(acc1, ah[kt][0], ah[kt][1], ah[kt][2], ah[kt][3], L.z, L.w);
            mma16816(acc0, al[kt][0], al[kt][1], al[kt][2], al[kt][3], H.x, H.y);
            mma16816(acc1, al[kt][0], al[kt][1], al[kt][2], al[kt][3], H.z, H.w);
        }
#pragma unroll
        for (int half = 0; half < 2; half++) {
            const float* accP = half ? acc1 : acc0;
            const int col = ntp * 16 + half * 8 + 2 * tig;
            if (col < FIN) {
                float2 bd = *(const float2*)&b_dec[col];
                float h00 = fmaxf(accP[0] * nd0 + bd.x, 0.f);
                float h01 = fmaxf(accP[1] * nd0 + bd.y, 0.f);
                float h10 = fmaxf(accP[2] * nd1 + bd.x, 0.f);
                float h11 = fmaxf(accP[3] * nd1 + bd.y, 0.f);
                float2 o0 = *(const float2*)(ori0 + col);
                float2 o1 = *(const float2*)(ori1 + col);
                shh0 += h00 * h00 + h01 * h01;
                sho0 += h00 * o0.x + h01 * o0.y;
                soo0 += o0.x * o0.x + o0.y * o0.y;
                shh1 += h10 * h10 + h11 * h11;
                sho1 += h10 * o1.x + h11 * o1.y;
                soo1 += o1.x * o1.x + o1.y * o1.y;
            }
        }
    }

    // reduce across the 4 tig lanes of each group
#pragma unroll
    for (int st = 1; st < 4; st <<= 1) {
        shh0 += __shfl_xor_sync(0xffffffffu, shh0, st);
        sho0 += __shfl_xor_sync(0xffffffffu, sho0, st);
        soo0 += __shfl_xor_sync(0xffffffffu, soo0, st);
        shh1 += __shfl_xor_sync(0xffffffffu, shh1, st);
        sho1 += __shfl_xor_sync(0xffffffffu, sho1, st);
        soo1 += __shfl_xor_sync(0xffffffffu, soo1, st);
    }
    if (tig == 0) {
        float inv0 = 1.f / fmaxf(sqrtf(shh0), 1e-12f);
        float inv1 = 1.f / fmaxf(sqrtf(shh1), 1e-12f);
        sErow[w * 16 + grp]     = shh0 * inv0 * inv0 - 2.f * inv0 * sho0 + soo0;
        sErow[w * 16 + grp + 8] = shh1 * inv1 * inv1 - 2.f * inv1 * sho1 + soo1;
    }
    __syncthreads();

    // CTA partials: Σe_dec0, Σe_dec1, Σlt1, Σlt2 over this CTA's 64 graphs
    float vE0 = 0.f, vE1 = 0.f;
    if (tid < 128) {
        float e = sErow[tid];
        if ((tid & 1) == 0) vE0 = e; else vE1 = e;
    }
    const int gb = blockIdx.x * 64;
    float E0 = bsum(vE0, sR);
    float E1 = bsum(vE1, sR);
    float L1 = bsum((tid < 64) ? g_lt1[gb + tid] : 0.f, sR);
    float L2 = bsum((tid < 64) ? g_lt2[gb + tid] : 0.f, sR);
    if (tid == 0) {
        g_part[blockIdx.x * 4 + 0] = E0;
        g_part[blockIdx.x * 4 + 1] = E1;
        g_part[blockIdx.x * 4 + 2] = L1;
        g_part[blockIdx.x * 4 + 3] = L2;
    }
}

// ===========================================================================
// Kernel 4: finalize -> out[0], g_gen.  Kernel 5: scores.
// ===========================================================================
__global__ void __launch_bounds__(256) finalize2(float* out) {
    __shared__ float sR[256];
    int tid = threadIdx.x;
    float a = (tid < 128) ? g_part[tid * 4 + 0] : 0.f;
    float c = (tid < 128) ? g_part[tid * 4 + 1] : 0.f;
    float m1 = (tid < 128) ? g_part[tid * 4 + 2] : 0.f;
    float m2 = (tid < 128) ? g_part[tid * 4 + 3] : 0.f;
    float Ssq1 = bsum(a, sR);
    float Ssq2 = bsum(c, sR);
    float M1 = bsum(m1, sR);
    float M2 = bsum(m2, sR);
    if (tid == 0) {
        float L_con = -(M1 / (float)Bsz + M2 / (float)Bsz) * 0.25f;
        float L_gen = (Ssq1 + Ssq2) / (2.f * (float)Bsz * (float)FIN);
        out[0] = ALPHA * L_con + BETA * L_gen;
        g_gen = (sqrtf(Ssq1) + sqrtf(Ssq2)) / (2.f * sqrtf((float)FIN));
    }
}

__global__ void scores_kernel(float* out) {
    int i = blockIdx.x * blockDim.x + threadIdx.x;
    if (i < Bsz) out[1 + i] = ALPHA * g_contr[i] + BETA * g_gen;
}

// ===========================================================================
extern "C" void kernel_launch(void* const* d_in, const int* in_sizes, int n_in,
                              void* d_out, int out_size) {
    const float* feat_p1 = (const float*)d_in[0];
    const float* feat_p2 = (const float*)d_in[1];
    const float* feat_n  = (const float*)d_in[2];
    const float* w_p1    = (const float*)d_in[3];
    const float* w_p2    = (const float*)d_in[4];
    const float* w_n     = (const float*)d_in[5];
    const float* W_enc   = (const float*)d_in[6];
    const float* b_enc   = (const float*)d_in[7];
    const float* W_dec   = (const float*)d_in[8];
    const float* b_dec   = (const float*)d_in[9];
    const float* W_bil   = (const float*)d_in[10];
    const float* b_bil   = (const float*)d_in[11];
    const int* src_p1 = (const int*)d_in[12];
    const int* dst_p1 = (const int*)d_in[13];
    const int* src_p2 = (const int*)d_in[14];
    const int* dst_p2 = (const int*)d_in[15];
    const int* src_n  = (const int*)d_in[16];
    const int* dst_n  = (const int*)d_in[17];
    float* out = (float*)d_out;

    cudaFuncSetAttribute(gemm_mma, cudaFuncAttributeMaxDynamicSharedMemorySize, GEMM_SMEM);
    cudaFuncSetAttribute(graph_kernel, cudaFuncAttributeMaxDynamicSharedMemorySize, GK_SMEM);

    prep_W<<<38, 256>>>(W_enc, W_dec);
    gemm_mma<<<3072, 256, GEMM_SMEM>>>(feat_p1, feat_p2, feat_n);

    graph_kernel<<<Bsz / 8, 256, GK_SMEM>>>(
        w_p1, w_p2, w_n, b_enc, W_bil, b_bil,
        src_p1, dst_p1, src_p2, dst_p2, src_n, dst_n);

    dec_err<<<128, 256>>>(feat_p1, feat_p2, b_dec);
    finalize2<<<1, 256>>>(out);
    scores_kernel<<<(Bsz + 255) / 256, 256>>>(out);
}